// round 2
// baseline (speedup 1.0000x reference)
#include <cuda_runtime.h>

typedef unsigned long long u64;

__device__ __forceinline__ u64 pack2(float a, float b) {
    u64 r;
    asm("mov.b64 %0, {%1, %2};" : "=l"(r)
        : "r"(__float_as_uint(a)), "r"(__float_as_uint(b)));
    return r;
}

__device__ __forceinline__ void unpack2(u64 v, float& a, float& b) {
    unsigned lo, hi;
    asm("mov.b64 {%0, %1}, %2;" : "=r"(lo), "=r"(hi) : "l"(v));
    a = __uint_as_float(lo);
    b = __uint_as_float(hi);
}

// out[i] = relu((1 - sigmoid(x@Wxz + bxz + bhz)) * tanh(x@Wxh + bxh + bhh)) @ Wlin + blin
// (H=0 => R-path and Wh* matmuls vanish; edge inputs are mathematically unused for K=1 ChebConv)
__global__ void __launch_bounds__(256) gconv_gru_fused(
    const float* __restrict__ x,
    const float* __restrict__ Wxz, const float* __restrict__ bxz, const float* __restrict__ bhz,
    const float* __restrict__ Wxh, const float* __restrict__ bxh, const float* __restrict__ bhh,
    const float* __restrict__ Wlin, const float* __restrict__ blin,
    float* __restrict__ out, int n)
{
    // Combined weight tile: sW[k][c], c in [0,64): cols 0..31 -> Wxz, 32..63 -> Wxh
    __shared__ float sW[16 * 64];
    __shared__ float sBias[64];   // [0,32): bxz+bhz ; [32,64): bxh+bhh
    __shared__ float sWlin[32];
    __shared__ float sBlin;

    const int tid = threadIdx.x;
    for (int idx = tid; idx < 1024; idx += 256) {
        int k = idx >> 6, c = idx & 63;
        sW[idx] = (c < 32) ? Wxz[k * 32 + c] : Wxh[k * 32 + (c - 32)];
    }
    if (tid < 64) sBias[tid] = (tid < 32) ? (bxz[tid] + bhz[tid])
                                          : (bxh[tid - 32] + bhh[tid - 32]);
    if (tid < 32) sWlin[tid] = Wlin[tid];
    if (tid == 0) sBlin = blin[0];
    __syncthreads();

    const int i = blockIdx.x * 256 + tid;
    if (i >= n) return;

    // Load the 16-dim feature row with 4x float4
    const float4* xp = reinterpret_cast<const float4*>(x) + (size_t)i * 4;
    float4 v0 = xp[0], v1 = xp[1], v2 = xp[2], v3 = xp[3];
    float xs[16] = { v0.x, v0.y, v0.z, v0.w,
                     v1.x, v1.y, v1.z, v1.w,
                     v2.x, v2.y, v2.z, v2.w,
                     v3.x, v3.y, v3.z, v3.w };

    // 32 packed-f32x2 accumulators: pairs 0..15 = Z pre-act cols, 16..31 = H~ pre-act cols
    u64 acc[32];
    const u64* bias2 = reinterpret_cast<const u64*>(sBias);
#pragma unroll
    for (int j = 0; j < 32; j++) acc[j] = bias2[j];

#pragma unroll
    for (int k = 0; k < 16; k++) {
        const u64 xk2 = pack2(xs[k], xs[k]);
        const u64* w2 = reinterpret_cast<const u64*>(sW + k * 64);
#pragma unroll
        for (int j = 0; j < 32; j++) {
            asm("fma.rn.f32x2 %0, %1, %2, %0;"
                : "+l"(acc[j]) : "l"(xk2), "l"(w2[j]));
        }
    }

    // Epilogue: gates + relu + final dot with Wlin
    float res = sBlin;
#pragma unroll
    for (int j = 0; j < 16; j++) {
        float a0, a1, c0, c1;
        unpack2(acc[j],      a0, a1);   // Z pre-activation, cols 2j, 2j+1
        unpack2(acc[16 + j], c0, c1);   // H~ pre-activation

        float z0 = __fdividef(1.0f, 1.0f + __expf(-a0));
        float z1 = __fdividef(1.0f, 1.0f + __expf(-a1));
        float e0 = __expf(2.0f * c0);
        float e1 = __expf(2.0f * c1);
        float t0 = 1.0f - __fdividef(2.0f, e0 + 1.0f);   // tanh(c0)
        float t1 = 1.0f - __fdividef(2.0f, e1 + 1.0f);   // tanh(c1)

        float p0 = (1.0f - z0) * t0;
        float p1 = (1.0f - z1) * t1;
        res += fmaxf(p0, 0.0f) * sWlin[2 * j]
             + fmaxf(p1, 0.0f) * sWlin[2 * j + 1];
    }
    out[i] = res;
}

extern "C" void kernel_launch(void* const* d_in, const int* in_sizes, int n_in,
                              void* d_out, int out_size)
{
    // Input order (metadata): 0=x, 1=edge_index(int64, unused), 2=edge_weight(unused),
    // 3=Wxz, 4=bxz, 5=Whz(unused), 6=bhz, 7=Wxr(unused), 8=bxr(unused), 9=Whr(unused),
    // 10=bhr(unused), 11=Wxh, 12=bxh, 13=Whh(unused), 14=bhh, 15=Wlin, 16=blin
    const float* x    = (const float*)d_in[0];
    const float* Wxz  = (const float*)d_in[3];
    const float* bxz  = (const float*)d_in[4];
    const float* bhz  = (const float*)d_in[6];
    const float* Wxh  = (const float*)d_in[11];
    const float* bxh  = (const float*)d_in[12];
    const float* bhh  = (const float*)d_in[14];
    const float* Wlin = (const float*)d_in[15];
    const float* blin = (const float*)d_in[16];

    const int n = in_sizes[0] / 16;
    const int blocks = (n + 255) / 256;
    gconv_gru_fused<<<blocks, 256>>>(x, Wxz, bxz, bhz, Wxh, bxh, bhh,
                                     Wlin, blin, (float*)d_out, n);
}

// round 4
// speedup vs baseline: 1.8971x; 1.8971x over previous
#include <cuda_runtime.h>

typedef unsigned long long u64;

__device__ __forceinline__ u64 pack2(float a, float b) {
    u64 r;
    asm("mov.b64 %0, {%1, %2};" : "=l"(r)
        : "r"(__float_as_uint(a)), "r"(__float_as_uint(b)));
    return r;
}

__device__ __forceinline__ void unpack2(u64 v, float& a, float& b) {
    unsigned lo, hi;
    asm("mov.b64 {%0, %1}, %2;" : "=r"(lo), "=r"(hi) : "l"(v));
    a = __uint_as_float(lo);
    b = __uint_as_float(hi);
}

// out[i] = relu((1 - sigmoid(x@Wxz + bxz + bhz)) * tanh(x@Wxh + bxh + bhh)) @ Wlin + blin
// (H=0 => R-path and Wh* matmuls vanish; edge inputs mathematically unused for K=1 ChebConv)
//
// Thread layout: thread pair (2p, 2p+1) covers nodes (n0, n1); each thread computes
// HALF (h = tid&1) of the 64 combined output columns for BOTH nodes, so every
// shared-weight LDS.64 feeds two FFMA2 (halves L1 wavefront traffic vs 1-node/thread).
__global__ void __launch_bounds__(128) gconv_gru_fused(
    const float* __restrict__ x,
    const float* __restrict__ Wxz, const float* __restrict__ bxz, const float* __restrict__ bhz,
    const float* __restrict__ Wxh, const float* __restrict__ bxh, const float* __restrict__ bhh,
    const float* __restrict__ Wlin, const float* __restrict__ blin,
    float* __restrict__ out, int n)
{
    // sW[k][c], c in [0,32): Wxz cols, [32,64): Wxh cols
    __shared__ float sW[16 * 64];
    __shared__ float sBias[64];   // [0,32): bxz+bhz ; [32,64): bxh+bhh
    __shared__ float sWlin[32];
    __shared__ float sBlin;

    const int tid = threadIdx.x;
    for (int idx = tid; idx < 1024; idx += 128) {
        int k = idx >> 6, c = idx & 63;
        sW[idx] = (c < 32) ? Wxz[k * 32 + c] : Wxh[k * 32 + (c - 32)];
    }
    if (tid < 64) sBias[tid] = (tid < 32) ? (bxz[tid] + bhz[tid])
                                          : (bxh[tid - 32] + bhh[tid - 32]);
    if (tid < 32) sWlin[tid] = Wlin[tid];
    if (tid == 0) sBlin = blin[0];
    __syncthreads();

    const int pair = tid >> 1;
    const int h    = tid & 1;        // column half this thread owns
    const int n0   = blockIdx.x * 128 + pair;
    const int n1   = n0 + 64;
    if (n0 >= n) return;
    const bool has1 = (n1 < n);

    // Load both feature rows (16 floats each) with float4
    float xs0[16], xs1[16];
    {
        const float4* xp = reinterpret_cast<const float4*>(x) + (size_t)n0 * 4;
        float4 a = xp[0], b = xp[1], c = xp[2], d = xp[3];
        float t0[16] = { a.x,a.y,a.z,a.w, b.x,b.y,b.z,b.w, c.x,c.y,c.z,c.w, d.x,d.y,d.z,d.w };
#pragma unroll
        for (int k = 0; k < 16; k++) xs0[k] = t0[k];
    }
    if (has1) {
        const float4* xp = reinterpret_cast<const float4*>(x) + (size_t)n1 * 4;
        float4 a = xp[0], b = xp[1], c = xp[2], d = xp[3];
        float t1[16] = { a.x,a.y,a.z,a.w, b.x,b.y,b.z,b.w, c.x,c.y,c.z,c.w, d.x,d.y,d.z,d.w };
#pragma unroll
        for (int k = 0; k < 16; k++) xs1[k] = t1[k];
    } else {
#pragma unroll
        for (int k = 0; k < 16; k++) xs1[k] = 0.0f;
    }

    // Accumulators: acc*[j] j<8 = Z col-pairs (cols 16h+2j, 16h+2j+1),
    //               acc*[8+j]   = H~ col-pairs (same logical cols)
    u64 acc0[16], acc1[16];
    {
        const u64* bias2 = reinterpret_cast<const u64*>(sBias);
#pragma unroll
        for (int j = 0; j < 8; j++) {
            u64 bz = bias2[8 * h + j];
            u64 bh = bias2[16 + 8 * h + j];
            acc0[j] = bz;  acc0[8 + j] = bh;
            acc1[j] = bz;  acc1[8 + j] = bh;
        }
    }

#pragma unroll
    for (int k = 0; k < 16; k++) {
        const u64 x0 = pack2(xs0[k], xs0[k]);
        const u64 x1 = pack2(xs1[k], xs1[k]);
        const u64* w2 = reinterpret_cast<const u64*>(sW + k * 64);
#pragma unroll
        for (int j = 0; j < 8; j++) {
            const u64 wz = w2[8 * h + j];        // one LDS.64 ...
            const u64 wh = w2[16 + 8 * h + j];
            asm("fma.rn.f32x2 %0, %1, %2, %0;" : "+l"(acc0[j])     : "l"(x0), "l"(wz)); // ... 2 FFMA2
            asm("fma.rn.f32x2 %0, %1, %2, %0;" : "+l"(acc1[j])     : "l"(x1), "l"(wz));
            asm("fma.rn.f32x2 %0, %1, %2, %0;" : "+l"(acc0[8 + j]) : "l"(x0), "l"(wh));
            asm("fma.rn.f32x2 %0, %1, %2, %0;" : "+l"(acc1[8 + j]) : "l"(x1), "l"(wh));
        }
    }

    // Epilogue: p_c = (1 - sigmoid(a)) * tanh(c) = (1-e^{-2c}) / ((1+e^a)(1+e^{-2c}))
    float res0 = 0.0f, res1 = 0.0f;
#pragma unroll
    for (int j = 0; j < 8; j++) {
        const float wl0 = sWlin[16 * h + 2 * j];
        const float wl1 = sWlin[16 * h + 2 * j + 1];

        float a0, a1, c0, c1;
        unpack2(acc0[j],     a0, a1);
        unpack2(acc0[8 + j], c0, c1);
        {
            float ea0 = __expf(a0),          ea1 = __expf(a1);
            float u0  = __expf(-2.0f * c0),  u1  = __expf(-2.0f * c1);
            float p0  = __fdividef(1.0f - u0, (1.0f + ea0) * (1.0f + u0));
            float p1  = __fdividef(1.0f - u1, (1.0f + ea1) * (1.0f + u1));
            res0 += fmaxf(p0, 0.0f) * wl0 + fmaxf(p1, 0.0f) * wl1;
        }

        unpack2(acc1[j],     a0, a1);
        unpack2(acc1[8 + j], c0, c1);
        {
            float ea0 = __expf(a0),          ea1 = __expf(a1);
            float u0  = __expf(-2.0f * c0),  u1  = __expf(-2.0f * c1);
            float p0  = __fdividef(1.0f - u0, (1.0f + ea0) * (1.0f + u0));
            float p1  = __fdividef(1.0f - u1, (1.0f + ea1) * (1.0f + u1));
            res1 += fmaxf(p0, 0.0f) * wl0 + fmaxf(p1, 0.0f) * wl1;
        }
    }

    // Combine column halves across the thread pair
    const unsigned mask = 0xFFFFFFFFu;
    float o0 = res0 + __shfl_xor_sync(mask, res0, 1);
    float o1 = res1 + __shfl_xor_sync(mask, res1, 1);
    if (h == 0) {
        out[n0] = o0 + sBlin;
        if (has1) out[n1] = o1 + sBlin;
    }
}

extern "C" void kernel_launch(void* const* d_in, const int* in_sizes, int n_in,
                              void* d_out, int out_size)
{
    // 0=x, 1=edge_index(unused), 2=edge_weight(unused), 3=Wxz, 4=bxz, 5=Whz(u), 6=bhz,
    // 7=Wxr(u), 8=bxr(u), 9=Whr(u), 10=bhr(u), 11=Wxh, 12=bxh, 13=Whh(u), 14=bhh,
    // 15=Wlin, 16=blin
    const float* x    = (const float*)d_in[0];
    const float* Wxz  = (const float*)d_in[3];
    const float* bxz  = (const float*)d_in[4];
    const float* bhz  = (const float*)d_in[6];
    const float* Wxh  = (const float*)d_in[11];
    const float* bxh  = (const float*)d_in[12];
    const float* bhh  = (const float*)d_in[14];
    const float* Wlin = (const float*)d_in[15];
    const float* blin = (const float*)d_in[16];

    const int n = in_sizes[0] / 16;
    const int blocks = (n + 127) / 128;   // 128 nodes per block
    gconv_gru_fused<<<blocks, 128>>>(x, Wxz, bxz, bhz, Wxh, bxh, bhh,
                                     Wlin, blin, (float*)d_out, n);
}

// round 6
// speedup vs baseline: 3.5315x; 1.8615x over previous
#include <cuda_runtime.h>
#include <cuda_bf16.h>
#include <cstdint>

#define NBLK 296
#define NTHR 256
#define WARPS_PER_BLK (NTHR / 32)

static __device__ __forceinline__ float tanh_fast(float x) {
    float r; asm("tanh.approx.f32 %0, %1;" : "=f"(r) : "f"(x)); return r;
}

// pack two f32 into bf16x2 (lo = first element)
static __device__ __forceinline__ uint32_t bfpack(float lo, float hi) {
    __nv_bfloat162 v = __floats2bfloat162_rn(lo, hi);
    return *reinterpret_cast<uint32_t*>(&v);
}
static __device__ __forceinline__ float bfres(float x) {   // residual after bf16 rounding
    return x - __bfloat162float(__float2bfloat16_rn(x));
}

static __device__ __forceinline__ void mma_bf16(
    float& c0, float& c1, float& c2, float& c3,
    uint32_t a0, uint32_t a1, uint32_t a2, uint32_t a3,
    uint32_t b0, uint32_t b1)
{
    asm volatile(
        "mma.sync.aligned.m16n8k16.row.col.f32.bf16.bf16.f32 "
        "{%0,%1,%2,%3},{%4,%5,%6,%7},{%8,%9},{%0,%1,%2,%3};"
        : "+f"(c0), "+f"(c1), "+f"(c2), "+f"(c3)
        : "r"(a0), "r"(a1), "r"(a2), "r"(a3), "r"(b0), "r"(b1));
}

static __device__ __forceinline__ float2 ldx2(const float* __restrict__ x, int row, int col, int n) {
    if (row < n) return *reinterpret_cast<const float2*>(x + (size_t)row * 16 + col);
    return make_float2(0.0f, 0.0f);
}

// out[i] = relu((1 - sigmoid(x@Wz' + bz')) * tanh(x@Wh' + bh')) @ Wlin + blin
// H=0 collapses the GRU; edge inputs are unused (ChebConv K=1).
// GEMM C[n,64] = X[n,16] @ Wcat[16,64] done on tensor cores via mma.sync bf16
// with hi/lo split (3 products). Z-side weights/bias pre-scaled by 0.5 so
// 1-sigmoid(a) = 0.5*(1 - tanh(a_scaled)); the 0.5 is folded into Wlin.
__global__ void __launch_bounds__(NTHR) gru_mma_kernel(
    const float* __restrict__ x,
    const float* __restrict__ Wxz, const float* __restrict__ bxz,
    const float* __restrict__ bhz,
    const float* __restrict__ Wxh, const float* __restrict__ bxh,
    const float* __restrict__ bhh,
    const float* __restrict__ Wlin, const float* __restrict__ blin,
    float* __restrict__ out, int n)
{
    const int lane = threadIdx.x & 31;
    const int wid  = threadIdx.x >> 5;
    const int g    = lane >> 2;     // groupID: row within tile
    const int t    = lane & 3;      // thread-in-group: col pair / k pair

    // ---- one-time: weight fragments, biases, Wlin into registers ----------
    // B fragment lane mapping (m16n8k16): rows k = {2t, 2t+1, 2t+8, 2t+9}, col = g
    uint32_t bhi0[8], bhi1[8], blo0[8], blo1[8];
    float bias0[8], bias1[8];
#pragma unroll
    for (int j = 0; j < 8; j++) {
        const bool zside = (j < 4);
        const float sc = zside ? 0.5f : 1.0f;
        const float* W = zside ? Wxz : Wxh;
        const int c = zside ? (8 * j + g) : (8 * j + g - 32);
        const float w0 = sc * __ldg(&W[(2 * t)     * 32 + c]);
        const float w1 = sc * __ldg(&W[(2 * t + 1) * 32 + c]);
        const float w2 = sc * __ldg(&W[(2 * t + 8) * 32 + c]);
        const float w3 = sc * __ldg(&W[(2 * t + 9) * 32 + c]);
        bhi0[j] = bfpack(w0, w1);
        bhi1[j] = bfpack(w2, w3);
        blo0[j] = bfpack(bfres(w0), bfres(w1));
        blo1[j] = bfpack(bfres(w2), bfres(w3));

        const int bc = zside ? (8 * j + 2 * t) : (8 * j + 2 * t - 32);
        if (zside) {
            bias0[j] = 0.5f * (__ldg(&bxz[bc])     + __ldg(&bhz[bc]));
            bias1[j] = 0.5f * (__ldg(&bxz[bc + 1]) + __ldg(&bhz[bc + 1]));
        } else {
            bias0[j] = __ldg(&bxh[bc])     + __ldg(&bhh[bc]);
            bias1[j] = __ldg(&bxh[bc + 1]) + __ldg(&bhh[bc + 1]);
        }
    }
    float wl0[4], wl1[4];
#pragma unroll
    for (int j = 0; j < 4; j++) {
        wl0[j] = 0.5f * __ldg(&Wlin[8 * j + 2 * t]);
        wl1[j] = 0.5f * __ldg(&Wlin[8 * j + 2 * t + 1]);
    }
    const float bl = __ldg(&blin[0]);

    // ---- persistent grid-stride over 16-node tiles ------------------------
    const int ntiles = (n + 15) >> 4;
    const int stride = NBLK * WARPS_PER_BLK;
    int tile = blockIdx.x * WARPS_PER_BLK + wid;
    if (tile >= ntiles) return;

    // A fragment loads for lane: rows {base+g, base+g+8}, col pairs {2t, 2t+8}
    int base = tile * 16;
    float2 x00 = ldx2(x, base + g,     2 * t,     n);   // (row g,   cols 2t,2t+1)
    float2 x10 = ldx2(x, base + g + 8, 2 * t,     n);
    float2 x01 = ldx2(x, base + g,     2 * t + 8, n);   // (row g,   cols 2t+8,2t+9)
    float2 x11 = ldx2(x, base + g + 8, 2 * t + 8, n);

#pragma unroll 1
    while (true) {
        // convert current tile's A fragments (hi + lo split)
        const uint32_t ah0 = bfpack(x00.x, x00.y);
        const uint32_t ah1 = bfpack(x10.x, x10.y);
        const uint32_t ah2 = bfpack(x01.x, x01.y);
        const uint32_t ah3 = bfpack(x11.x, x11.y);
        const uint32_t al0 = bfpack(bfres(x00.x), bfres(x00.y));
        const uint32_t al1 = bfpack(bfres(x10.x), bfres(x10.y));
        const uint32_t al2 = bfpack(bfres(x01.x), bfres(x01.y));
        const uint32_t al3 = bfpack(bfres(x11.x), bfres(x11.y));

        const int cur_base = base;
        const int tnext = tile + stride;
        const bool hasnext = (tnext < ntiles);
        if (hasnext) {   // prefetch next tile's x under the MMA/epilogue
            base = tnext * 16;
            x00 = ldx2(x, base + g,     2 * t,     n);
            x10 = ldx2(x, base + g + 8, 2 * t,     n);
            x01 = ldx2(x, base + g,     2 * t + 8, n);
            x11 = ldx2(x, base + g + 8, 2 * t + 8, n);
        }

        // accumulators, init with bias
        float acc[8][4];
#pragma unroll
        for (int j = 0; j < 8; j++) {
            acc[j][0] = bias0[j]; acc[j][1] = bias1[j];
            acc[j][2] = bias0[j]; acc[j][3] = bias1[j];
        }
#pragma unroll
        for (int j = 0; j < 8; j++) {
            mma_bf16(acc[j][0], acc[j][1], acc[j][2], acc[j][3],
                     ah0, ah1, ah2, ah3, bhi0[j], bhi1[j]);   // x_hi * W_hi
            mma_bf16(acc[j][0], acc[j][1], acc[j][2], acc[j][3],
                     al0, al1, al2, al3, bhi0[j], bhi1[j]);   // x_lo * W_hi
            mma_bf16(acc[j][0], acc[j][1], acc[j][2], acc[j][3],
                     ah0, ah1, ah2, ah3, blo0[j], blo1[j]);   // x_hi * W_lo
        }

        // epilogue: tile j (Z) pairs with tile j+4 (H~), same lane positions
        float res0 = 0.0f, res1 = 0.0f;
#pragma unroll
        for (int j = 0; j < 4; j++) {
            float t1, t2, p;
            t1 = tanh_fast(acc[j][0]); t2 = tanh_fast(acc[j + 4][0]);
            p = t2 - t1 * t2; res0 = fmaf(fmaxf(p, 0.0f), wl0[j], res0);
            t1 = tanh_fast(acc[j][1]); t2 = tanh_fast(acc[j + 4][1]);
            p = t2 - t1 * t2; res0 = fmaf(fmaxf(p, 0.0f), wl1[j], res0);
            t1 = tanh_fast(acc[j][2]); t2 = tanh_fast(acc[j + 4][2]);
            p = t2 - t1 * t2; res1 = fmaf(fmaxf(p, 0.0f), wl0[j], res1);
            t1 = tanh_fast(acc[j][3]); t2 = tanh_fast(acc[j + 4][3]);
            p = t2 - t1 * t2; res1 = fmaf(fmaxf(p, 0.0f), wl1[j], res1);
        }

        // reduce over the 4 lanes of the group (t = 0..3)
        res0 += __shfl_xor_sync(0xFFFFFFFFu, res0, 1);
        res0 += __shfl_xor_sync(0xFFFFFFFFu, res0, 2);
        res1 += __shfl_xor_sync(0xFFFFFFFFu, res1, 1);
        res1 += __shfl_xor_sync(0xFFFFFFFFu, res1, 2);
        if (t == 0) {
            const int r0 = cur_base + g, r1 = cur_base + g + 8;
            if (r0 < n) out[r0] = res0 + bl;
            if (r1 < n) out[r1] = res1 + bl;
        }

        if (!hasnext) break;
        tile = tnext;
    }
}

extern "C" void kernel_launch(void* const* d_in, const int* in_sizes, int n_in,
                              void* d_out, int out_size)
{
    // 0=x, 1=edge_index(unused), 2=edge_weight(unused), 3=Wxz, 4=bxz, 5=Whz(u), 6=bhz,
    // 7=Wxr(u), 8=bxr(u), 9=Whr(u), 10=bhr(u), 11=Wxh, 12=bxh, 13=Whh(u), 14=bhh,
    // 15=Wlin, 16=blin
    const float* x    = (const float*)d_in[0];
    const float* Wxz  = (const float*)d_in[3];
    const float* bxz  = (const float*)d_in[4];
    const float* bhz  = (const float*)d_in[6];
    const float* Wxh  = (const float*)d_in[11];
    const float* bxh  = (const float*)d_in[12];
    const float* bhh  = (const float*)d_in[14];
    const float* Wlin = (const float*)d_in[15];
    const float* blin = (const float*)d_in[16];

    const int n = in_sizes[0] / 16;
    gru_mma_kernel<<<NBLK, NTHR>>>(x, Wxz, bxz, bhz, Wxh, bxh, bhh,
                                   Wlin, blin, (float*)d_out, n);
}

// round 7
// speedup vs baseline: 4.2546x; 1.2048x over previous
#include <cuda_runtime.h>
#include <cuda_bf16.h>
#include <cstdint>

#define NBLK 888            // 148 SMs * 6 CTAs
#define NTHR 128
#define WPB  (NTHR / 32)
#define NWARPS (NBLK * WPB)

static __device__ __forceinline__ float tanh_fast(float x) {
    float r; asm("tanh.approx.f32 %0, %1;" : "=f"(r) : "f"(x)); return r;
}
static __device__ __forceinline__ uint32_t bfpack(float lo, float hi) {
    __nv_bfloat162 v = __floats2bfloat162_rn(lo, hi);
    return *reinterpret_cast<uint32_t*>(&v);
}
static __device__ __forceinline__ float bfres(float x) {
    return x - __bfloat162float(__float2bfloat16_rn(x));
}
static __device__ __forceinline__ void mma_bf16(
    float& c0, float& c1, float& c2, float& c3,
    uint32_t a0, uint32_t a1, uint32_t a2, uint32_t a3,
    uint32_t b0, uint32_t b1)
{
    asm volatile(
        "mma.sync.aligned.m16n8k16.row.col.f32.bf16.bf16.f32 "
        "{%0,%1,%2,%3},{%4,%5,%6,%7},{%8,%9},{%0,%1,%2,%3};"
        : "+f"(c0), "+f"(c1), "+f"(c2), "+f"(c3)
        : "r"(a0), "r"(a1), "r"(a2), "r"(a3), "r"(b0), "r"(b1));
}
static __device__ __forceinline__ float2 ldx2g(const float* __restrict__ x, int row, int col, int n) {
    if (row < n) return *reinterpret_cast<const float2*>(x + (size_t)row * 16 + col);
    return make_float2(0.0f, 0.0f);
}

// out[i] = relu((1 - sigmoid(x@Wz' + bz')) * tanh(x@Wh' + bh')) @ Wlin + blin
// (H=0 collapses the GRU; edge inputs mathematically unused for ChebConv K=1.)
// Tensor-core GEMM via mma.sync bf16 with hi/lo split (3 products).
// All warp-invariant per-lane constants (B frags, biases, Wlin) are staged in
// shared memory by warp 0 and re-loaded per tile -> regs <= 84 -> 6 CTAs/SM.
__global__ void __launch_bounds__(NTHR, 6) gru_mma_kernel(
    const float* __restrict__ x,
    const float* __restrict__ Wxz, const float* __restrict__ bxz,
    const float* __restrict__ bhz,
    const float* __restrict__ Wxh, const float* __restrict__ bxh,
    const float* __restrict__ bhh,
    const float* __restrict__ Wlin, const float* __restrict__ blin,
    float* __restrict__ out, int n)
{
    __shared__ uint2  sBhi[8][32];   // (bhi0, bhi1) per lane per n-chunk
    __shared__ uint2  sBlo[8][32];   // (blo0, blo1)
    __shared__ float2 sBias[8][32];  // (bias0, bias1)
    __shared__ float2 sWl[4][32];    // (wl0, wl1), 0.5 folded in
    __shared__ float  sBl;

    const int lane = threadIdx.x & 31;
    const int wid  = threadIdx.x >> 5;
    const int g    = lane >> 2;
    const int t    = lane & 3;

    // ---- warp 0: stage lane-indexed constants into smem --------------------
    if (wid == 0) {
#pragma unroll
        for (int j = 0; j < 8; j++) {
            const bool zside = (j < 4);
            const float sc = zside ? 0.5f : 1.0f;
            const float* W = zside ? Wxz : Wxh;
            const int c = zside ? (8 * j + g) : (8 * (j - 4) + g);
            const float w0 = sc * __ldg(&W[(2 * t)     * 32 + c]);
            const float w1 = sc * __ldg(&W[(2 * t + 1) * 32 + c]);
            const float w2 = sc * __ldg(&W[(2 * t + 8) * 32 + c]);
            const float w3 = sc * __ldg(&W[(2 * t + 9) * 32 + c]);
            sBhi[j][lane] = make_uint2(bfpack(w0, w1), bfpack(w2, w3));
            sBlo[j][lane] = make_uint2(bfpack(bfres(w0), bfres(w1)),
                                       bfpack(bfres(w2), bfres(w3)));
            const int bc = zside ? (8 * j + 2 * t) : (8 * (j - 4) + 2 * t);
            float b0, b1;
            if (zside) {
                b0 = 0.5f * (__ldg(&bxz[bc])     + __ldg(&bhz[bc]));
                b1 = 0.5f * (__ldg(&bxz[bc + 1]) + __ldg(&bhz[bc + 1]));
            } else {
                b0 = __ldg(&bxh[bc])     + __ldg(&bhh[bc]);
                b1 = __ldg(&bxh[bc + 1]) + __ldg(&bhh[bc + 1]);
            }
            sBias[j][lane] = make_float2(b0, b1);
        }
#pragma unroll
        for (int j = 0; j < 4; j++)
            sWl[j][lane] = make_float2(0.5f * __ldg(&Wlin[8 * j + 2 * t]),
                                       0.5f * __ldg(&Wlin[8 * j + 2 * t + 1]));
        if (lane == 0) sBl = __ldg(&blin[0]);
    }
    __syncthreads();

    const int ntiles = (n + 15) >> 4;
    int tile = blockIdx.x * WPB + wid;
    if (tile >= ntiles) return;

    const float bl = sBl;
    const long long step = (long long)NWARPS * 256;
    const float* p = x + (size_t)tile * 256 + (size_t)(g * 16 + 2 * t);

    // initial load: rows {g, g+8}, col pairs {2t, 2t+8}
    float2 c00, c01, c10, c11;
    if (tile * 16 + 16 <= n) {
        c00 = *(const float2*)(p);
        c01 = *(const float2*)(p + 8);
        c10 = *(const float2*)(p + 128);
        c11 = *(const float2*)(p + 136);
    } else {
        const int b16 = tile * 16;
        c00 = ldx2g(x, b16 + g,     2 * t,     n);
        c01 = ldx2g(x, b16 + g,     2 * t + 8, n);
        c10 = ldx2g(x, b16 + g + 8, 2 * t,     n);
        c11 = ldx2g(x, b16 + g + 8, 2 * t + 8, n);
    }

#pragma unroll 1
    while (true) {
        // convert current tile's A fragments (hi + lo split)
        const uint32_t ah0 = bfpack(c00.x, c00.y);
        const uint32_t ah1 = bfpack(c10.x, c10.y);
        const uint32_t ah2 = bfpack(c01.x, c01.y);
        const uint32_t ah3 = bfpack(c11.x, c11.y);
        const uint32_t al0 = bfpack(bfres(c00.x), bfres(c00.y));
        const uint32_t al1 = bfpack(bfres(c10.x), bfres(c10.y));
        const uint32_t al2 = bfpack(bfres(c01.x), bfres(c01.y));
        const uint32_t al3 = bfpack(bfres(c11.x), bfres(c11.y));

        const int node0 = tile * 16 + g;
        const int tnext = tile + NWARPS;
        const bool hasnext = (tnext < ntiles);
        if (hasnext) {                      // prefetch next tile under MMA+epilogue
            p += step;
            if (tnext * 16 + 16 <= n) {
                c00 = *(const float2*)(p);
                c01 = *(const float2*)(p + 8);
                c10 = *(const float2*)(p + 128);
                c11 = *(const float2*)(p + 136);
            } else {
                const int b16 = tnext * 16;
                c00 = ldx2g(x, b16 + g,     2 * t,     n);
                c01 = ldx2g(x, b16 + g,     2 * t + 8, n);
                c10 = ldx2g(x, b16 + g + 8, 2 * t,     n);
                c11 = ldx2g(x, b16 + g + 8, 2 * t + 8, n);
            }
        }

        float acc[8][4];
#pragma unroll
        for (int j = 0; j < 8; j++) {
            const float2 bi = sBias[j][lane];
            const uint2  bh = sBhi[j][lane];
            acc[j][0] = bi.x; acc[j][1] = bi.y;
            acc[j][2] = bi.x; acc[j][3] = bi.y;
            mma_bf16(acc[j][0], acc[j][1], acc[j][2], acc[j][3],
                     ah0, ah1, ah2, ah3, bh.x, bh.y);       // x_hi * W_hi
            mma_bf16(acc[j][0], acc[j][1], acc[j][2], acc[j][3],
                     al0, al1, al2, al3, bh.x, bh.y);       // x_lo * W_hi
            const uint2 bl2 = sBlo[j][lane];
            mma_bf16(acc[j][0], acc[j][1], acc[j][2], acc[j][3],
                     ah0, ah1, ah2, ah3, bl2.x, bl2.y);     // x_hi * W_lo
        }

        // epilogue: chunk j (Z, pre-scaled 0.5) pairs with chunk j+4 (H~)
        float res0 = 0.0f, res1 = 0.0f;
#pragma unroll
        for (int j = 0; j < 4; j++) {
            const float2 w = sWl[j][lane];
            float t1, t2, pp;
            t1 = tanh_fast(acc[j][0]); t2 = tanh_fast(acc[j + 4][0]);
            pp = t2 - t1 * t2; res0 = fmaf(fmaxf(pp, 0.0f), w.x, res0);
            t1 = tanh_fast(acc[j][1]); t2 = tanh_fast(acc[j + 4][1]);
            pp = t2 - t1 * t2; res0 = fmaf(fmaxf(pp, 0.0f), w.y, res0);
            t1 = tanh_fast(acc[j][2]); t2 = tanh_fast(acc[j + 4][2]);
            pp = t2 - t1 * t2; res1 = fmaf(fmaxf(pp, 0.0f), w.x, res1);
            t1 = tanh_fast(acc[j][3]); t2 = tanh_fast(acc[j + 4][3]);
            pp = t2 - t1 * t2; res1 = fmaf(fmaxf(pp, 0.0f), w.y, res1);
        }

        res0 += __shfl_xor_sync(0xFFFFFFFFu, res0, 1);
        res0 += __shfl_xor_sync(0xFFFFFFFFu, res0, 2);
        res1 += __shfl_xor_sync(0xFFFFFFFFu, res1, 1);
        res1 += __shfl_xor_sync(0xFFFFFFFFu, res1, 2);
        if (t == 0) {
            if (node0 < n)     out[node0]     = res0 + bl;
            if (node0 + 8 < n) out[node0 + 8] = res1 + bl;
        }

        if (!hasnext) break;
        tile = tnext;
    }
}

extern "C" void kernel_launch(void* const* d_in, const int* in_sizes, int n_in,
                              void* d_out, int out_size)
{
    // 0=x, 1=edge_index(unused), 2=edge_weight(unused), 3=Wxz, 4=bxz, 5=Whz(u), 6=bhz,
    // 7=Wxr(u), 8=bxr(u), 9=Whr(u), 10=bhr(u), 11=Wxh, 12=bxh, 13=Whh(u), 14=bhh,
    // 15=Wlin, 16=blin
    const float* x    = (const float*)d_in[0];
    const float* Wxz  = (const float*)d_in[3];
    const float* bxz  = (const float*)d_in[4];
    const float* bhz  = (const float*)d_in[6];
    const float* Wxh  = (const float*)d_in[11];
    const float* bxh  = (const float*)d_in[12];
    const float* bhh  = (const float*)d_in[14];
    const float* Wlin = (const float*)d_in[15];
    const float* blin = (const float*)d_in[16];

    const int n = in_sizes[0] / 16;
    gru_mma_kernel<<<NBLK, NTHR>>>(x, Wxz, bxz, bhz, Wxh, bxh, bhh,
                                   Wlin, blin, (float*)d_out, n);
}

// round 8
// speedup vs baseline: 4.3059x; 1.0121x over previous
#include <cuda_runtime.h>
#include <cuda_bf16.h>
#include <cstdint>

#define NCTA_SM 7
#define NBLK (148 * NCTA_SM)
#define NTHR 128
#define WPB  (NTHR / 32)
#define NWARPS (NBLK * WPB)

static __device__ __forceinline__ float tanh_fast(float x) {
    float r; asm("tanh.approx.f32 %0, %1;" : "=f"(r) : "f"(x)); return r;
}
static __device__ __forceinline__ uint32_t bfpack(float lo, float hi) {
    __nv_bfloat162 v = __floats2bfloat162_rn(lo, hi);
    return *reinterpret_cast<uint32_t*>(&v);
}
static __device__ __forceinline__ float bfres(float x) {
    return x - __bfloat162float(__float2bfloat16_rn(x));
}
// high 16 bits of two f32 -> bf16x2 (truncation split)
static __device__ __forceinline__ uint32_t hi2(float a, float b) {
    uint32_t r;
    asm("prmt.b32 %0, %1, %2, 0x7632;" : "=r"(r)
        : "r"(__float_as_uint(a)), "r"(__float_as_uint(b)));
    return r;
}
static __device__ __forceinline__ float trunc_res(float x) {
    return x - __uint_as_float(__float_as_uint(x) & 0xFFFF0000u);
}
static __device__ __forceinline__ void mma_bf16(
    float& c0, float& c1, float& c2, float& c3,
    uint32_t a0, uint32_t a1, uint32_t a2, uint32_t a3,
    uint32_t b0, uint32_t b1)
{
    asm volatile(
        "mma.sync.aligned.m16n8k16.row.col.f32.bf16.bf16.f32 "
        "{%0,%1,%2,%3},{%4,%5,%6,%7},{%8,%9},{%0,%1,%2,%3};"
        : "+f"(c0), "+f"(c1), "+f"(c2), "+f"(c3)
        : "r"(a0), "r"(a1), "r"(a2), "r"(a3), "r"(b0), "r"(b1));
}
static __device__ __forceinline__ float2 ldx2g(const float* __restrict__ x, int row, int col, int n) {
    if (row < n) return *reinterpret_cast<const float2*>(x + (size_t)row * 16 + col);
    return make_float2(0.0f, 0.0f);
}

// out[i] = relu((1 - sigmoid(x@Wz' + bz')) * tanh(x@Wh' + bh')) @ Wlin + blin
// (H=0 collapses the GRU; edge inputs mathematically unused for ChebConv K=1.)
// Tensor-core GEMM via mma.sync bf16, hi/lo truncation split (3 products).
// Warp-invariant per-lane constants staged in smem as 16B-packed vectors.
__global__ void __launch_bounds__(NTHR, NCTA_SM) gru_mma_kernel(
    const float* __restrict__ x,
    const float* __restrict__ Wxz, const float* __restrict__ bxz,
    const float* __restrict__ bhz,
    const float* __restrict__ Wxh, const float* __restrict__ bxh,
    const float* __restrict__ bhh,
    const float* __restrict__ Wlin, const float* __restrict__ blin,
    float* __restrict__ out, int n)
{
    __shared__ uint4  sB[8][32];     // (bhi0, bhi1, blo0, blo1) per lane per n-chunk
    __shared__ float4 sBias[4][32];  // (z0, z1, h0, h1) for chunk pair (j, j+4)
    __shared__ float4 sWl[2][32];    // (wl0[j], wl1[j], wl0[j+1], wl1[j+1]), 0.5 folded
    __shared__ float  sBl;

    const int lane = threadIdx.x & 31;
    const int wid  = threadIdx.x >> 5;
    const int g    = lane >> 2;
    const int t    = lane & 3;

    // ---- warp 0: stage lane-indexed constants ------------------------------
    if (wid == 0) {
#pragma unroll
        for (int j = 0; j < 8; j++) {
            const bool zside = (j < 4);
            const float sc = zside ? 0.5f : 1.0f;
            const float* W = zside ? Wxz : Wxh;
            const int c = zside ? (8 * j + g) : (8 * (j - 4) + g);
            const float w0 = sc * __ldg(&W[(2 * t)     * 32 + c]);
            const float w1 = sc * __ldg(&W[(2 * t + 1) * 32 + c]);
            const float w2 = sc * __ldg(&W[(2 * t + 8) * 32 + c]);
            const float w3 = sc * __ldg(&W[(2 * t + 9) * 32 + c]);
            sB[j][lane] = make_uint4(bfpack(w0, w1), bfpack(w2, w3),
                                     bfpack(bfres(w0), bfres(w1)),
                                     bfpack(bfres(w2), bfres(w3)));
        }
#pragma unroll
        for (int j = 0; j < 4; j++) {
            const int zc = 8 * j + 2 * t;
            sBias[j][lane] = make_float4(
                0.5f * (__ldg(&bxz[zc])     + __ldg(&bhz[zc])),
                0.5f * (__ldg(&bxz[zc + 1]) + __ldg(&bhz[zc + 1])),
                __ldg(&bxh[zc])     + __ldg(&bhh[zc]),
                __ldg(&bxh[zc + 1]) + __ldg(&bhh[zc + 1]));
        }
#pragma unroll
        for (int j = 0; j < 2; j++)
            sWl[j][lane] = make_float4(
                0.5f * __ldg(&Wlin[16 * j + 2 * t]),
                0.5f * __ldg(&Wlin[16 * j + 2 * t + 1]),
                0.5f * __ldg(&Wlin[16 * j + 8 + 2 * t]),
                0.5f * __ldg(&Wlin[16 * j + 8 + 2 * t + 1]));
        if (lane == 0) sBl = __ldg(&blin[0]);
    }
    __syncthreads();

    const int ntiles = (n + 15) >> 4;
    int tile = blockIdx.x * WPB + wid;
    if (tile >= ntiles) return;

    const float bl = sBl;
    const long long step = (long long)NWARPS * 256;
    const float* p = x + (size_t)tile * 256 + (size_t)(g * 16 + 2 * t);

    float2 c00, c01, c10, c11;
    if (tile * 16 + 16 <= n) {
        c00 = *(const float2*)(p);
        c01 = *(const float2*)(p + 8);
        c10 = *(const float2*)(p + 128);
        c11 = *(const float2*)(p + 136);
    } else {
        const int b16 = tile * 16;
        c00 = ldx2g(x, b16 + g,     2 * t,     n);
        c01 = ldx2g(x, b16 + g,     2 * t + 8, n);
        c10 = ldx2g(x, b16 + g + 8, 2 * t,     n);
        c11 = ldx2g(x, b16 + g + 8, 2 * t + 8, n);
    }

#pragma unroll 1
    while (true) {
        // A fragments: truncation hi + exact residual rounded to bf16
        const uint32_t ah0 = hi2(c00.x, c00.y);
        const uint32_t ah1 = hi2(c10.x, c10.y);
        const uint32_t ah2 = hi2(c01.x, c01.y);
        const uint32_t ah3 = hi2(c11.x, c11.y);
        const uint32_t al0 = bfpack(trunc_res(c00.x), trunc_res(c00.y));
        const uint32_t al1 = bfpack(trunc_res(c10.x), trunc_res(c10.y));
        const uint32_t al2 = bfpack(trunc_res(c01.x), trunc_res(c01.y));
        const uint32_t al3 = bfpack(trunc_res(c11.x), trunc_res(c11.y));

        const int node0 = tile * 16 + g;
        const int tnext = tile + NWARPS;
        const bool hasnext = (tnext < ntiles);
        if (hasnext) {                      // prefetch next tile under MMA+epilogue
            p += step;
            if (tnext * 16 + 16 <= n) {
                c00 = *(const float2*)(p);
                c01 = *(const float2*)(p + 8);
                c10 = *(const float2*)(p + 128);
                c11 = *(const float2*)(p + 136);
            } else {
                const int b16 = tnext * 16;
                c00 = ldx2g(x, b16 + g,     2 * t,     n);
                c01 = ldx2g(x, b16 + g,     2 * t + 8, n);
                c10 = ldx2g(x, b16 + g + 8, 2 * t,     n);
                c11 = ldx2g(x, b16 + g + 8, 2 * t + 8, n);
            }
        }

        float acc[8][4];
#pragma unroll
        for (int j = 0; j < 4; j++) {
            const float4 bi = sBias[j][lane];
            acc[j][0] = bi.x;     acc[j][1] = bi.y;
            acc[j][2] = bi.x;     acc[j][3] = bi.y;
            acc[j + 4][0] = bi.z; acc[j + 4][1] = bi.w;
            acc[j + 4][2] = bi.z; acc[j + 4][3] = bi.w;
        }
#pragma unroll
        for (int j = 0; j < 8; j++) {
            const uint4 b = sB[j][lane];
            mma_bf16(acc[j][0], acc[j][1], acc[j][2], acc[j][3],
                     ah0, ah1, ah2, ah3, b.x, b.y);   // x_hi * W_hi
            mma_bf16(acc[j][0], acc[j][1], acc[j][2], acc[j][3],
                     al0, al1, al2, al3, b.x, b.y);   // x_lo * W_hi
            mma_bf16(acc[j][0], acc[j][1], acc[j][2], acc[j][3],
                     ah0, ah1, ah2, ah3, b.z, b.w);   // x_hi * W_lo
        }

        // epilogue: chunk j (Z, pre-scaled 0.5) pairs with chunk j+4 (H~)
        float r0a = 0.0f, r0b = 0.0f, r1a = 0.0f, r1b = 0.0f;
#pragma unroll
        for (int j = 0; j < 4; j++) {
            const float4 w4 = sWl[j >> 1][lane];
            const float wx = (j & 1) ? w4.z : w4.x;
            const float wy = (j & 1) ? w4.w : w4.y;
            float t1, t2, pp;
            t1 = tanh_fast(acc[j][0]); t2 = tanh_fast(acc[j + 4][0]);
            pp = t2 - t1 * t2; r0a = fmaf(fmaxf(pp, 0.0f), wx, r0a);
            t1 = tanh_fast(acc[j][1]); t2 = tanh_fast(acc[j + 4][1]);
            pp = t2 - t1 * t2; r0b = fmaf(fmaxf(pp, 0.0f), wy, r0b);
            t1 = tanh_fast(acc[j][2]); t2 = tanh_fast(acc[j + 4][2]);
            pp = t2 - t1 * t2; r1a = fmaf(fmaxf(pp, 0.0f), wx, r1a);
            t1 = tanh_fast(acc[j][3]); t2 = tanh_fast(acc[j + 4][3]);
            pp = t2 - t1 * t2; r1b = fmaf(fmaxf(pp, 0.0f), wy, r1b);
        }
        float res0 = r0a + r0b, res1 = r1a + r1b;

        res0 += __shfl_xor_sync(0xFFFFFFFFu, res0, 1);
        res0 += __shfl_xor_sync(0xFFFFFFFFu, res0, 2);
        res1 += __shfl_xor_sync(0xFFFFFFFFu, res1, 1);
        res1 += __shfl_xor_sync(0xFFFFFFFFu, res1, 2);
        if (t == 0) {
            if (node0 < n)     out[node0]     = res0 + bl;
            if (node0 + 8 < n) out[node0 + 8] = res1 + bl;
        }

        if (!hasnext) break;
        tile = tnext;
    }
}

extern "C" void kernel_launch(void* const* d_in, const int* in_sizes, int n_in,
                              void* d_out, int out_size)
{
    // 0=x, 1=edge_index(unused), 2=edge_weight(unused), 3=Wxz, 4=bxz, 5=Whz(u), 6=bhz,
    // 7=Wxr(u), 8=bxr(u), 9=Whr(u), 10=bhr(u), 11=Wxh, 12=bxh, 13=Whh(u), 14=bhh,
    // 15=Wlin, 16=blin
    const float* x    = (const float*)d_in[0];
    const float* Wxz  = (const float*)d_in[3];
    const float* bxz  = (const float*)d_in[4];
    const float* bhz  = (const float*)d_in[6];
    const float* Wxh  = (const float*)d_in[11];
    const float* bxh  = (const float*)d_in[12];
    const float* bhh  = (const float*)d_in[14];
    const float* Wlin = (const float*)d_in[15];
    const float* blin = (const float*)d_in[16];

    const int n = in_sizes[0] / 16;
    gru_mma_kernel<<<NBLK, NTHR>>>(x, Wxz, bxz, bhz, Wxh, bxh, bhh,
                                   Wlin, blin, (float*)d_out, n);
}

// round 10
// speedup vs baseline: 4.5823x; 1.0642x over previous
#include <cuda_runtime.h>
#include <cuda_bf16.h>
#include <cstdint>

#define NCTA_SM 6
#define NBLK (148 * NCTA_SM)
#define NTHR 128
#define WPB  (NTHR / 32)
#define NWARPS (NBLK * WPB)

static __device__ __forceinline__ float tanh_fast(float x) {
    float r; asm("tanh.approx.f32 %0, %1;" : "=f"(r) : "f"(x)); return r;
}
static __device__ __forceinline__ uint32_t bfpack(float lo, float hi) {
    __nv_bfloat162 v = __floats2bfloat162_rn(lo, hi);
    return *reinterpret_cast<uint32_t*>(&v);
}
static __device__ __forceinline__ float bfres(float x) {
    return x - __bfloat162float(__float2bfloat16_rn(x));
}
// high 16 bits of two f32 -> bf16x2 (truncation split)
static __device__ __forceinline__ uint32_t hi2(float a, float b) {
    uint32_t r;
    asm("prmt.b32 %0, %1, %2, 0x7632;" : "=r"(r)
        : "r"(__float_as_uint(a)), "r"(__float_as_uint(b)));
    return r;
}
static __device__ __forceinline__ float trunc_res(float x) {
    return x - __uint_as_float(__float_as_uint(x) & 0xFFFF0000u);
}
static __device__ __forceinline__ void mma_bf16(
    float& c0, float& c1, float& c2, float& c3,
    uint32_t a0, uint32_t a1, uint32_t a2, uint32_t a3,
    uint32_t b0, uint32_t b1)
{
    asm volatile(
        "mma.sync.aligned.m16n8k16.row.col.f32.bf16.bf16.f32 "
        "{%0,%1,%2,%3},{%4,%5,%6,%7},{%8,%9},{%0,%1,%2,%3};"
        : "+f"(c0), "+f"(c1), "+f"(c2), "+f"(c3)
        : "r"(a0), "r"(a1), "r"(a2), "r"(a3), "r"(b0), "r"(b1));
}
static __device__ __forceinline__ float2 ldx2g(const float* __restrict__ x, int row, int col, int n) {
    if (row < n) return *reinterpret_cast<const float2*>(x + (size_t)row * 16 + col);
    return make_float2(0.0f, 0.0f);
}

// out[i] = relu((1 - sigmoid(x@Wz' + bz')) * tanh(x@Wh' + bh')) @ Wlin + blin
// (H=0 collapses the GRU; edge inputs mathematically unused for ChebConv K=1.)
// mma.sync bf16, 3-product hi/lo split (x and W both split; validated rel~9e-6).
// Each warp processes 32 nodes (two m16 A-sets) per iteration sharing one
// B-frag/bias/Wlin reload; chunk-pair loop keeps only 16 accs live.
__global__ void __launch_bounds__(NTHR, NCTA_SM) gru_mma_kernel(
    const float* __restrict__ x,
    const float* __restrict__ Wxz, const float* __restrict__ bxz,
    const float* __restrict__ bhz,
    const float* __restrict__ Wxh, const float* __restrict__ bxh,
    const float* __restrict__ bhh,
    const float* __restrict__ Wlin, const float* __restrict__ blin,
    float* __restrict__ out, int n)
{
    __shared__ uint4  sB[8][32];     // (hi0, hi1, lo0, lo1) per lane per n-chunk
    __shared__ float4 sBias[4][32];  // (z0, z1, h0, h1) for chunk pair (j, j+4)
    __shared__ float2 sWl[4][32];    // (wl0, wl1) per chunk pair, 0.5 folded
    __shared__ float  sBl;

    const int lane = threadIdx.x & 31;
    const int wid  = threadIdx.x >> 5;
    const int g    = lane >> 2;
    const int t    = lane & 3;

    // ---- warp 0: stage lane-indexed constants ------------------------------
    if (wid == 0) {
#pragma unroll
        for (int j = 0; j < 8; j++) {
            const bool zside = (j < 4);
            const float sc = zside ? 0.5f : 1.0f;
            const float* W = zside ? Wxz : Wxh;
            const int c = zside ? (8 * j + g) : (8 * (j - 4) + g);
            const float w0 = sc * __ldg(&W[(2 * t)     * 32 + c]);
            const float w1 = sc * __ldg(&W[(2 * t + 1) * 32 + c]);
            const float w2 = sc * __ldg(&W[(2 * t + 8) * 32 + c]);
            const float w3 = sc * __ldg(&W[(2 * t + 9) * 32 + c]);
            sB[j][lane] = make_uint4(bfpack(w0, w1), bfpack(w2, w3),
                                     bfpack(bfres(w0), bfres(w1)),
                                     bfpack(bfres(w2), bfres(w3)));
        }
#pragma unroll
        for (int j = 0; j < 4; j++) {
            const int zc = 8 * j + 2 * t;
            sBias[j][lane] = make_float4(
                0.5f * (__ldg(&bxz[zc])     + __ldg(&bhz[zc])),
                0.5f * (__ldg(&bxz[zc + 1]) + __ldg(&bhz[zc + 1])),
                __ldg(&bxh[zc])     + __ldg(&bhh[zc]),
                __ldg(&bxh[zc + 1]) + __ldg(&bhh[zc + 1]));
            sWl[j][lane] = make_float2(0.5f * __ldg(&Wlin[zc]),
                                       0.5f * __ldg(&Wlin[zc + 1]));
        }
        if (lane == 0) sBl = __ldg(&blin[0]);
    }
    __syncthreads();

    const int nt32 = (n + 31) >> 5;               // 32-node tiles
    int tile = blockIdx.x * WPB + wid;
    if (tile >= nt32) return;

    const float bl = sBl;
    const long long step = (long long)NWARPS * 512;
    const float* p = x + (size_t)tile * 512 + (size_t)(g * 16 + 2 * t);

    // current-iteration x values: tile A rows {g, g+8}, tile B rows {16+g, 24+g}
    float2 c00, c01, c10, c11, d00, d01, d10, d11;
    if (tile * 32 + 32 <= n) {
        c00 = *(const float2*)(p);        c01 = *(const float2*)(p + 8);
        c10 = *(const float2*)(p + 128);  c11 = *(const float2*)(p + 136);
        d00 = *(const float2*)(p + 256);  d01 = *(const float2*)(p + 264);
        d10 = *(const float2*)(p + 384);  d11 = *(const float2*)(p + 392);
    } else {
        const int b = tile * 32;
        c00 = ldx2g(x, b + g,      2 * t,     n);
        c01 = ldx2g(x, b + g,      2 * t + 8, n);
        c10 = ldx2g(x, b + g + 8,  2 * t,     n);
        c11 = ldx2g(x, b + g + 8,  2 * t + 8, n);
        d00 = ldx2g(x, b + g + 16, 2 * t,     n);
        d01 = ldx2g(x, b + g + 16, 2 * t + 8, n);
        d10 = ldx2g(x, b + g + 24, 2 * t,     n);
        d11 = ldx2g(x, b + g + 24, 2 * t + 8, n);
    }

#pragma unroll 1
    while (true) {
        // A fragments for both 16-row sets: truncation hi + bf16 residual lo
        const uint32_t ahA0 = hi2(c00.x, c00.y), ahA1 = hi2(c10.x, c10.y);
        const uint32_t ahA2 = hi2(c01.x, c01.y), ahA3 = hi2(c11.x, c11.y);
        const uint32_t alA0 = bfpack(trunc_res(c00.x), trunc_res(c00.y));
        const uint32_t alA1 = bfpack(trunc_res(c10.x), trunc_res(c10.y));
        const uint32_t alA2 = bfpack(trunc_res(c01.x), trunc_res(c01.y));
        const uint32_t alA3 = bfpack(trunc_res(c11.x), trunc_res(c11.y));
        const uint32_t ahB0 = hi2(d00.x, d00.y), ahB1 = hi2(d10.x, d10.y);
        const uint32_t ahB2 = hi2(d01.x, d01.y), ahB3 = hi2(d11.x, d11.y);
        const uint32_t alB0 = bfpack(trunc_res(d00.x), trunc_res(d00.y));
        const uint32_t alB1 = bfpack(trunc_res(d10.x), trunc_res(d10.y));
        const uint32_t alB2 = bfpack(trunc_res(d01.x), trunc_res(d01.y));
        const uint32_t alB3 = bfpack(trunc_res(d11.x), trunc_res(d11.y));

        const int node0 = tile * 32 + g;
        const int tnext = tile + NWARPS;
        const bool hasnext = (tnext < nt32);
        if (hasnext) {                      // prefetch next tile under MMA+epilogue
            p += step;
            if (tnext * 32 + 32 <= n) {
                c00 = *(const float2*)(p);        c01 = *(const float2*)(p + 8);
                c10 = *(const float2*)(p + 128);  c11 = *(const float2*)(p + 136);
                d00 = *(const float2*)(p + 256);  d01 = *(const float2*)(p + 264);
                d10 = *(const float2*)(p + 384);  d11 = *(const float2*)(p + 392);
            } else {
                const int b = tnext * 32;
                c00 = ldx2g(x, b + g,      2 * t,     n);
                c01 = ldx2g(x, b + g,      2 * t + 8, n);
                c10 = ldx2g(x, b + g + 8,  2 * t,     n);
                c11 = ldx2g(x, b + g + 8,  2 * t + 8, n);
                d00 = ldx2g(x, b + g + 16, 2 * t,     n);
                d01 = ldx2g(x, b + g + 16, 2 * t + 8, n);
                d10 = ldx2g(x, b + g + 24, 2 * t,     n);
                d11 = ldx2g(x, b + g + 24, 2 * t + 8, n);
            }
        }

        float r0 = 0.0f, r1 = 0.0f, r2 = 0.0f, r3 = 0.0f;
#pragma unroll
        for (int jp = 0; jp < 4; jp++) {
            const uint4  bz = sB[jp][lane];        // Z-side W frags (hi, lo)
            const uint4  bh = sB[jp + 4][lane];    // H-side W frags
            const float4 bi = sBias[jp][lane];
            const float2 w  = sWl[jp][lane];

            float zA0 = bi.x, zA1 = bi.y, zA2 = bi.x, zA3 = bi.y;
            float hA0 = bi.z, hA1 = bi.w, hA2 = bi.z, hA3 = bi.w;
            float zB0 = bi.x, zB1 = bi.y, zB2 = bi.x, zB3 = bi.y;
            float hB0 = bi.z, hB1 = bi.w, hB2 = bi.z, hB3 = bi.w;

            mma_bf16(zA0, zA1, zA2, zA3, ahA0, ahA1, ahA2, ahA3, bz.x, bz.y);
            mma_bf16(zB0, zB1, zB2, zB3, ahB0, ahB1, ahB2, ahB3, bz.x, bz.y);
            mma_bf16(hA0, hA1, hA2, hA3, ahA0, ahA1, ahA2, ahA3, bh.x, bh.y);
            mma_bf16(hB0, hB1, hB2, hB3, ahB0, ahB1, ahB2, ahB3, bh.x, bh.y);
            mma_bf16(zA0, zA1, zA2, zA3, alA0, alA1, alA2, alA3, bz.x, bz.y);
            mma_bf16(zB0, zB1, zB2, zB3, alB0, alB1, alB2, alB3, bz.x, bz.y);
            mma_bf16(hA0, hA1, hA2, hA3, alA0, alA1, alA2, alA3, bh.x, bh.y);
            mma_bf16(hB0, hB1, hB2, hB3, alB0, alB1, alB2, alB3, bh.x, bh.y);
            mma_bf16(zA0, zA1, zA2, zA3, ahA0, ahA1, ahA2, ahA3, bz.z, bz.w);
            mma_bf16(zB0, zB1, zB2, zB3, ahB0, ahB1, ahB2, ahB3, bz.z, bz.w);
            mma_bf16(hA0, hA1, hA2, hA3, ahA0, ahA1, ahA2, ahA3, bh.z, bh.w);
            mma_bf16(hB0, hB1, hB2, hB3, ahB0, ahB1, ahB2, ahB3, bh.z, bh.w);

            // epilogue for this chunk pair: p = (1 - t1) * t2, 0.5 in wlin
            float t1, t2, pp;
            t1 = tanh_fast(zA0); t2 = tanh_fast(hA0);
            pp = t2 - t1 * t2; r0 = fmaf(fmaxf(pp, 0.0f), w.x, r0);
            t1 = tanh_fast(zA1); t2 = tanh_fast(hA1);
            pp = t2 - t1 * t2; r0 = fmaf(fmaxf(pp, 0.0f), w.y, r0);
            t1 = tanh_fast(zA2); t2 = tanh_fast(hA2);
            pp = t2 - t1 * t2; r1 = fmaf(fmaxf(pp, 0.0f), w.x, r1);
            t1 = tanh_fast(zA3); t2 = tanh_fast(hA3);
            pp = t2 - t1 * t2; r1 = fmaf(fmaxf(pp, 0.0f), w.y, r1);
            t1 = tanh_fast(zB0); t2 = tanh_fast(hB0);
            pp = t2 - t1 * t2; r2 = fmaf(fmaxf(pp, 0.0f), w.x, r2);
            t1 = tanh_fast(zB1); t2 = tanh_fast(hB1);
            pp = t2 - t1 * t2; r2 = fmaf(fmaxf(pp, 0.0f), w.y, r2);
            t1 = tanh_fast(zB2); t2 = tanh_fast(hB2);
            pp = t2 - t1 * t2; r3 = fmaf(fmaxf(pp, 0.0f), w.x, r3);
            t1 = tanh_fast(zB3); t2 = tanh_fast(hB3);
            pp = t2 - t1 * t2; r3 = fmaf(fmaxf(pp, 0.0f), w.y, r3);
        }

        r0 += __shfl_xor_sync(0xFFFFFFFFu, r0, 1);
        r0 += __shfl_xor_sync(0xFFFFFFFFu, r0, 2);
        r1 += __shfl_xor_sync(0xFFFFFFFFu, r1, 1);
        r1 += __shfl_xor_sync(0xFFFFFFFFu, r1, 2);
        r2 += __shfl_xor_sync(0xFFFFFFFFu, r2, 1);
        r2 += __shfl_xor_sync(0xFFFFFFFFu, r2, 2);
        r3 += __shfl_xor_sync(0xFFFFFFFFu, r3, 1);
        r3 += __shfl_xor_sync(0xFFFFFFFFu, r3, 2);
        if (t == 0) {
            if (node0 < n)      out[node0]      = r0 + bl;
            if (node0 + 8 < n)  out[node0 + 8]  = r1 + bl;
            if (node0 + 16 < n) out[node0 + 16] = r2 + bl;
            if (node0 + 24 < n) out[node0 + 24] = r3 + bl;
        }

        if (!hasnext) break;
        tile = tnext;
    }
}

extern "C" void kernel_launch(void* const* d_in, const int* in_sizes, int n_in,
                              void* d_out, int out_size)
{
    // 0=x, 1=edge_index(unused), 2=edge_weight(unused), 3=Wxz, 4=bxz, 5=Whz(u), 6=bhz,
    // 7=Wxr(u), 8=bxr(u), 9=Whr(u), 10=bhr(u), 11=Wxh, 12=bxh, 13=Whh(u), 14=bhh,
    // 15=Wlin, 16=blin
    const float* x    = (const float*)d_in[0];
    const float* Wxz  = (const float*)d_in[3];
    const float* bxz  = (const float*)d_in[4];
    const float* bhz  = (const float*)d_in[6];
    const float* Wxh  = (const float*)d_in[11];
    const float* bxh  = (const float*)d_in[12];
    const float* bhh  = (const float*)d_in[14];
    const float* Wlin = (const float*)d_in[15];
    const float* blin = (const float*)d_in[16];

    const int n = in_sizes[0] / 16;
    gru_mma_kernel<<<NBLK, NTHR>>>(x, Wxz, bxz, bhz, Wxh, bxh, bhh,
                                   Wlin, blin, (float*)d_out, n);
}